// round 12
// baseline (speedup 1.0000x reference)
#include <cuda_runtime.h>
#include <cuda_fp16.h>
#include <stdint.h>
#include <math.h>

#define T_TOK 2048
#define DMODEL 1024
#define HID 2048
#define NEXP 8
#define PADROWS 5120          // 4096 routed rows + per-expert pad to 128
#define MAXTILE 40            // PADROWS / 128

// ======================= scratch (device globals) =======================
__device__ int   g_cnt[NEXP];
__device__ int   g_fill[NEXP];
__device__ int   g_off[NEXP + 1];     // padded offsets (multiples of 128)
__device__ int   g_tok[PADROWS];      // routed row -> token (-1 = pad)
__device__ int   g_pos[2 * T_TOK];    // (t,k) -> routed row
__device__ int   g_topi[2 * T_TOK];
__device__ float g_topw[2 * T_TOK];

// tiled fp16 operands: each (tile, kchunk) block = 128 rows x 64 cols = 16KB,
// SW128-swizzled within 128B rows. Contiguous per block -> cp.async.bulk.
__device__ __align__(128) __half g_At[(size_t)MAXTILE * 16 * 8192];
__device__ __align__(128) __half g_Ht[(size_t)MAXTILE * 32 * 8192];
__device__ __align__(128) __half g_W1t[(size_t)NEXP * 16 * 16 * 8192];
__device__ __align__(128) __half g_W2t[(size_t)NEXP * 8 * 32 * 8192];
__device__ float g_Y[(size_t)PADROWS * DMODEL];

// ======================= helpers =======================
__device__ __forceinline__ uint32_t smem_u32(const void* p) {
    uint32_t a;
    asm("{ .reg .u64 t; cvta.to.shared.u64 t, %1; cvt.u32.u64 %0, t; }" : "=r"(a) : "l"(p));
    return a;
}
__device__ __forceinline__ void bulkcp(uint32_t dst, const void* src,
                                       uint32_t bytes, uint32_t mbar) {
    asm volatile(
        "cp.async.bulk.shared::cta.global.mbarrier::complete_tx::bytes "
        "[%0], [%1], %2, [%3];"
        :: "r"(dst), "l"(src), "r"(bytes), "r"(mbar) : "memory");
}
#define FENCE_PROXY_ASYNC() asm volatile("fence.proxy.async.shared::cta;" ::: "memory")
#define MBARRIER_INIT(a, c) \
    asm volatile("mbarrier.init.shared.b64 [%0], %1;" :: "r"((uint32_t)(a)), "r"((uint32_t)(c)) : "memory")
#define MBARRIER_EXPECT_TX(a, b) \
    asm volatile("mbarrier.arrive.expect_tx.shared.b64 _, [%0], %1;" :: "r"((uint32_t)(a)), "r"((uint32_t)(b)) : "memory")
#define MBARRIER_WAIT_PARITY(mbar_smem_addr, phase_parity) do { \
    uint32_t _mbar = (uint32_t)(mbar_smem_addr); \
    uint32_t _parity = (uint32_t)(phase_parity); \
    uint32_t _done; \
    asm volatile( \
        "{\n\t.reg .pred p;\n\t" \
        "mbarrier.try_wait.parity.acquire.cta.shared::cta.b64 p, [%1], %2;\n\t" \
        "selp.b32 %0, 1, 0, p;\n\t}" \
        : "=r"(_done) : "r"(_mbar), "r"(_parity) : "memory"); \
    if (!_done) { \
        asm volatile( \
            "{\n\t.reg .pred P1;\n\t" \
            "WAIT_LOOP_%=:\n\t" \
            "mbarrier.try_wait.parity.acquire.cta.shared::cta.b64 P1, [%0], %1, 0x989680;\n\t" \
            "@P1 bra.uni WAIT_DONE_%=;\n\t" \
            "bra.uni WAIT_LOOP_%=;\n\t" \
            "WAIT_DONE_%=:\n\t}" \
            :: "r"(_mbar), "r"(_parity) : "memory"); \
    } \
} while (0)

__device__ __forceinline__ void ldsm_x4(uint32_t* r, uint32_t addr) {
    asm volatile("ldmatrix.sync.aligned.m8n8.x4.shared.b16 {%0,%1,%2,%3}, [%4];"
                 : "=r"(r[0]), "=r"(r[1]), "=r"(r[2]), "=r"(r[3]) : "r"(addr));
}
__device__ __forceinline__ void mma16816(float* d, const uint32_t* a, const uint32_t* b) {
    asm volatile(
        "mma.sync.aligned.m16n8k16.row.col.f32.f16.f16.f32 "
        "{%0,%1,%2,%3}, {%4,%5,%6,%7}, {%8,%9}, {%0,%1,%2,%3};"
        : "+f"(d[0]), "+f"(d[1]), "+f"(d[2]), "+f"(d[3])
        : "r"(a[0]), "r"(a[1]), "r"(a[2]), "r"(a[3]), "r"(b[0]), "r"(b[1]));
}
__device__ __forceinline__ uint32_t packh2(float a, float b) {
    __half2 h = __halves2half2(__float2half_rn(a), __float2half_rn(b));
    return *reinterpret_cast<uint32_t*>(&h);
}
// swizzled byte offset within a 128B tile row
__device__ __forceinline__ uint32_t swz(uint32_t boff, uint32_t row) {
    return boff ^ ((row & 7u) << 4);
}

// ======================= routing =======================
__global__ void zero_kernel() {
    int i = blockIdx.x * 256 + threadIdx.x;
    if (i < PADROWS) g_tok[i] = -1;
    if (i < NEXP) { g_cnt[i] = 0; g_fill[i] = 0; }
}

__global__ void scan_kernel() {
    g_off[0] = 0;
    for (int e = 0; e < NEXP; e++)
        g_off[e + 1] = g_off[e] + ((g_cnt[e] + 127) & ~127);
}

__global__ void scatter_kernel() {
    int t = blockIdx.x * blockDim.x + threadIdx.x;
    if (t >= T_TOK) return;
    #pragma unroll
    for (int k = 0; k < 2; k++) {
        int e = g_topi[2 * t + k];
        int p = g_off[e] + atomicAdd(&g_fill[e], 1);
        g_tok[p] = t;
        g_pos[2 * t + k] = p;
    }
}

__global__ void gate_kernel(const float* __restrict__ X,
                            const float* __restrict__ Wg,
                            const float* __restrict__ bg,
                            float* __restrict__ out) {
    int gwarp = (blockIdx.x * blockDim.x + threadIdx.x) >> 5;
    int lane = threadIdx.x & 31;
    if (gwarp >= T_TOK) return;
    int t = gwarp;
    float p[NEXP];
    #pragma unroll
    for (int e = 0; e < NEXP; e++) p[e] = 0.0f;
    for (int d = lane; d < DMODEL; d += 32) {
        float x = X[(size_t)t * DMODEL + d];
        const float* w = Wg + (size_t)d * NEXP;
        #pragma unroll
        for (int e = 0; e < NEXP; e++) p[e] += x * w[e];
    }
    #pragma unroll
    for (int s = 16; s > 0; s >>= 1)
        #pragma unroll
        for (int e = 0; e < NEXP; e++)
            p[e] += __shfl_xor_sync(0xFFFFFFFF, p[e], s);
    if (lane == 0) {
        float lg[NEXP];
        #pragma unroll
        for (int e = 0; e < NEXP; e++) lg[e] = p[e] + bg[e];
        int i0 = 0; float v0 = lg[0];
        #pragma unroll
        for (int e = 1; e < NEXP; e++) if (lg[e] > v0) { v0 = lg[e]; i0 = e; }
        int i1 = -1; float v1 = -3.4e38f;
        #pragma unroll
        for (int e = 0; e < NEXP; e++)
            if (e != i0 && lg[e] > v1) { v1 = lg[e]; i1 = e; }
        float ex = expf(v1 - v0);
        float inv = 1.0f / (1.0f + ex);
        g_topi[2 * t] = i0;     g_topi[2 * t + 1] = i1;
        g_topw[2 * t] = inv;    g_topw[2 * t + 1] = ex * inv;
        atomicAdd(&g_cnt[i0], 1);
        atomicAdd(&g_cnt[i1], 1);
        out[(size_t)T_TOK * DMODEL + 2 * t]     = (float)i0;
        out[(size_t)T_TOK * DMODEL + 2 * t + 1] = (float)i1;
    }
}

// ======================= A-tile build: gather + fp16 + tile + swizzle ======
__global__ void atile_kernel(const float* __restrict__ X) {
    int tile = blockIdx.x;
    int kc = blockIdx.y;
    int row = threadIdx.x >> 1;
    int half = threadIdx.x & 1;
    int p = tile * 128 + row;
    int tok = g_tok[p];

    float v[32];
    if (tok >= 0) {
        const float* src = X + (size_t)tok * DMODEL + kc * 64 + half * 32;
        #pragma unroll
        for (int j = 0; j < 32; j += 4) {
            float4 f = *reinterpret_cast<const float4*>(src + j);
            v[j] = f.x; v[j + 1] = f.y; v[j + 2] = f.z; v[j + 3] = f.w;
        }
    } else {
        #pragma unroll
        for (int j = 0; j < 32; j++) v[j] = 0.0f;
    }

    size_t base = ((size_t)tile * 16 + kc) * 8192 + (size_t)row * 64;
    #pragma unroll
    for (int u = 0; u < 4; u++) {
        uint32_t w[4];
        #pragma unroll
        for (int q = 0; q < 4; q++)
            w[q] = packh2(v[u * 8 + q * 2], v[u * 8 + q * 2 + 1]);
        uint32_t bo = swz(half * 64 + u * 16, row);
        *reinterpret_cast<uint4*>(reinterpret_cast<char*>(g_At + base) + bo) =
            make_uint4(w[0], w[1], w[2], w[3]);
    }
}

// ======================= W-tile build: transpose + fp16 + tile + swizzle ===
// WHICH=0 -> g_W1t, WHICH=1 -> g_W2t (selected in DEVICE code).
template <int WHICH>
__global__ void wtile_kernel(const float* __restrict__ W, int KD, int ND) {
    __shared__ float s[64][132];
    int nb = blockIdx.x, kc = blockIdx.y, e = blockIdx.z;
    const float* Wp = W + (size_t)e * KD * ND + (size_t)kc * 64 * ND + nb * 128;
    int tid = threadIdx.x;
    #pragma unroll
    for (int i = 0; i < 32; i++) {
        int lin = tid + i * 256;          // 0..8191
        int kk = lin >> 7, nn = lin & 127;
        s[kk][nn] = Wp[(size_t)kk * ND + nn];
    }
    __syncthreads();
    __half* O = (WHICH == 0) ? g_W1t : g_W2t;
    int nkch = KD >> 6;
    size_t base = (((size_t)e * (ND >> 7) + nb) * nkch + kc) * 8192;
    #pragma unroll
    for (int i = 0; i < 4; i++) {
        int uu = tid + i * 256;           // 0..1023
        int r = uu >> 3, seg = uu & 7;
        uint32_t w[4];
        #pragma unroll
        for (int q = 0; q < 4; q++)
            w[q] = packh2(s[seg * 8 + q * 2][r], s[seg * 8 + q * 2 + 1][r]);
        uint32_t bo = swz(seg * 16, r);
        *reinterpret_cast<uint4*>(reinterpret_cast<char*>(O + base) + (size_t)r * 128 + bo) =
            make_uint4(w[0], w[1], w[2], w[3]);
    }
}

// ======================= GEMM: 128x256 CTA tile, 64x64 warp tile =======================
// LAYER=0: A = g_At, B = g_W1t, gelu epilogue -> tiled H (fp16).
// LAYER=1: A = g_Ht, B = g_W2t, plain epilogue -> g_Y (fp32).
// Stage: A plane 16KB + B rows 0..255 contiguous 32KB = 48KB. 3 stages.
#define APLANE 16384
#define STAGE 49152
#define NST 3
#define GSMEM (NST * STAGE + 64)   // 147520

template <int NKCH, int NDIM, int LAYER>
__global__ void __launch_bounds__(256)
tc_gemm(const float* __restrict__ biasBase) {
    const int e = blockIdx.z;
    const int m0 = blockIdx.x * 128;
    if (m0 >= g_cnt[e]) return;
    const int p0 = g_off[e] + m0;           // multiple of 128
    const int tile = p0 >> 7;
    const int by = blockIdx.y;              // 256-wide n block

    extern __shared__ __align__(128) char smem[];
    const uint32_t sb = smem_u32(smem);
    const uint32_t mb = sb + NST * STAGE;
    const int tid = threadIdx.x;
    const int wid = tid >> 5;
    const int lane = tid & 31;

    if (tid == 0) {
        MBARRIER_INIT(mb, 1);
        MBARRIER_INIT(mb + 8, 1);
        MBARRIER_INIT(mb + 16, 1);
        FENCE_PROXY_ASYNC();
    }
    __syncthreads();

    // device-side symbol references (NEVER passed from host)
    const __half* Ab = (LAYER == 0) ? g_At : g_Ht;
    const __half* Bb = (LAYER == 0) ? g_W1t : g_W2t;

    const __half* asrc  = Ab + (size_t)tile * NKCH * 8192;
    const __half* bsrc0 = Bb + (((size_t)e * (NDIM >> 7) + 2 * by)     * NKCH) * 8192;
    const __half* bsrc1 = Bb + (((size_t)e * (NDIM >> 7) + 2 * by + 1) * NKCH) * 8192;

    // prologue: chunks 0 and 1 into stages 0 and 1
    if (tid == 0) {
        #pragma unroll
        for (int s = 0; s < 2; s++) {
            uint32_t so = sb + s * STAGE;
            size_t go = (size_t)s * 8192;
            MBARRIER_EXPECT_TX(mb + s * 8, STAGE);
            bulkcp(so,                    asrc  + go, APLANE, mb + s * 8);
            bulkcp(so + APLANE,           bsrc0 + go, APLANE, mb + s * 8);
            bulkcp(so + APLANE + APLANE,  bsrc1 + go, APLANE, mb + s * 8);
        }
    }

    float acc[4][8][4];
    #pragma unroll
    for (int mi = 0; mi < 4; mi++)
        #pragma unroll
        for (int ni = 0; ni < 8; ni++)
            #pragma unroll
            for (int j = 0; j < 4; j++) acc[mi][ni][j] = 0.0f;

    const int wm = wid & 1;      // 2 m-groups of 64
    const int wn = wid >> 1;     // 4 n-groups of 64
    const uint32_t a_row = wm * 64 + (lane & 15);
    const uint32_t b_row = wn * 64 + (lane & 7);     // B rows 0..255 contiguous
    const uint32_t a_sw = (lane >> 4) * 16;
    const uint32_t b_sw = (lane >> 3) * 16;

    for (int c = 0; c < NKCH; c++) {
        int st = c % NST;
        if (c + 2 < NKCH && tid == 0) {
            int sn = (c + 2) % NST;
            uint32_t so = sb + sn * STAGE;
            uint32_t mbn = mb + sn * 8;
            size_t go = (size_t)(c + 2) * 8192;
            MBARRIER_EXPECT_TX(mbn, STAGE);
            bulkcp(so,                   asrc  + go, APLANE, mbn);
            bulkcp(so + APLANE,          bsrc0 + go, APLANE, mbn);
            bulkcp(so + APLANE + APLANE, bsrc1 + go, APLANE, mbn);
        }
        MBARRIER_WAIT_PARITY(mb + st * 8, (c / NST) & 1);

        uint32_t stg = sb + st * STAGE;
        #pragma unroll
        for (int pair = 0; pair < 2; pair++) {
            // B fragments: 8 n8-groups, x4 covers both k16 of the pair
            uint32_t bfr[8][4];
            #pragma unroll
            for (int ni = 0; ni < 8; ni++) {
                uint32_t r = b_row + ni * 8;
                ldsm_x4(bfr[ni], stg + APLANE + r * 128 + swz(pair * 64 + b_sw, r));
            }
            uint32_t afr0[4][4], afr1[4][4];
            #pragma unroll
            for (int mi = 0; mi < 4; mi++) {
                uint32_t r = a_row + mi * 16;
                ldsm_x4(afr0[mi], stg + r * 128 + swz((pair * 2) * 32 + a_sw, r));
            }
            #pragma unroll
            for (int mi = 0; mi < 4; mi++) {
                uint32_t r = a_row + mi * 16;
                ldsm_x4(afr1[mi], stg + r * 128 + swz((pair * 2 + 1) * 32 + a_sw, r));
            }
            #pragma unroll
            for (int mi = 0; mi < 4; mi++)
                #pragma unroll
                for (int ni = 0; ni < 8; ni++)
                    mma16816(acc[mi][ni], afr0[mi], &bfr[ni][0]);
            #pragma unroll
            for (int mi = 0; mi < 4; mi++)
                #pragma unroll
                for (int ni = 0; ni < 8; ni++)
                    mma16816(acc[mi][ni], afr1[mi], &bfr[ni][2]);
        }
        __syncthreads();   // stage st free for refill at c+3
    }

    // ---- epilogue ----
    const float* bias = biasBase + (size_t)e * NDIM;
    #pragma unroll
    for (int mi = 0; mi < 4; mi++) {
        #pragma unroll
        for (int half = 0; half < 2; half++) {
            int ml = wm * 64 + mi * 16 + (lane >> 2) + half * 8;
            #pragma unroll
            for (int ni = 0; ni < 8; ni++) {
                int n = by * 256 + wn * 64 + ni * 8 + (lane & 3) * 2;
                float v0 = acc[mi][ni][half * 2]     + bias[n];
                float v1 = acc[mi][ni][half * 2 + 1] + bias[n + 1];
                if (LAYER == 0) {
                    float c0 = v0 * v0 * v0, c1 = v1 * v1 * v1;
                    v0 = 0.5f * v0 * (1.0f + tanhf(0.7978845608028654f * (v0 + 0.044715f * c0)));
                    v1 = 0.5f * v1 * (1.0f + tanhf(0.7978845608028654f * (v1 + 0.044715f * c1)));
                    // write H in GEMM2's tiled layout: [tile][n>>6][128 rows][128B sw]
                    size_t bbase = (((size_t)tile * 32 + (n >> 6)) * 128 + ml) * 128;
                    uint32_t bo = swz((n & 63) * 2, ml);
                    *reinterpret_cast<uint32_t*>(
                        reinterpret_cast<char*>(g_Ht) + bbase + bo) = packh2(v0, v1);
                } else {
                    float2 f; f.x = v0; f.y = v1;
                    *reinterpret_cast<float2*>(&g_Y[(size_t)(p0 + ml) * NDIM + n]) = f;
                }
            }
        }
    }
}

// ======================= combine =======================
__global__ void combine_kernel(float* __restrict__ out) {
    int i = blockIdx.x * 256 + threadIdx.x;
    int t = i >> 10;
    int d = i & 1023;
    int p0 = g_pos[2 * t], p1 = g_pos[2 * t + 1];
    float w0 = g_topw[2 * t], w1 = g_topw[2 * t + 1];
    out[i] = w0 * g_Y[(size_t)p0 * DMODEL + d] +
             w1 * g_Y[(size_t)p1 * DMODEL + d];
}

// ======================= launch =======================
extern "C" void kernel_launch(void* const* d_in, const int* in_sizes, int n_in,
                              void* d_out, int out_size) {
    const float* X  = (const float*)d_in[0];
    const float* Wg = (const float*)d_in[1];
    const float* bg = (const float*)d_in[2];
    const float* W1 = (const float*)d_in[3];
    const float* b1 = (const float*)d_in[4];
    const float* W2 = (const float*)d_in[5];
    const float* b2 = (const float*)d_in[6];
    float* out = (float*)d_out;

    cudaFuncSetAttribute(tc_gemm<16, HID, 0>,
                         cudaFuncAttributeMaxDynamicSharedMemorySize, GSMEM);
    cudaFuncSetAttribute(tc_gemm<32, DMODEL, 1>,
                         cudaFuncAttributeMaxDynamicSharedMemorySize, GSMEM);

    zero_kernel<<<20, 256>>>();
    gate_kernel<<<T_TOK / 8, 256>>>(X, Wg, bg, out);
    scan_kernel<<<1, 1>>>();
    scatter_kernel<<<8, 256>>>();

    atile_kernel<<<dim3(MAXTILE, 16), 256>>>(X);
    wtile_kernel<0><<<dim3(HID / 128, DMODEL / 64, NEXP), 256>>>(W1, DMODEL, HID);
    wtile_kernel<1><<<dim3(DMODEL / 128, HID / 64, NEXP), 256>>>(W2, HID, DMODEL);

    tc_gemm<16, HID, 0>
        <<<dim3(32, HID / 256, NEXP), 256, GSMEM>>>(b1);
    tc_gemm<32, DMODEL, 1>
        <<<dim3(32, DMODEL / 256, NEXP), 256, GSMEM>>>(b2);

    combine_kernel<<<(T_TOK * DMODEL) / 256, 256>>>(out);
}

// round 13
// speedup vs baseline: 1.1619x; 1.1619x over previous
#include <cuda_runtime.h>
#include <cuda_fp16.h>
#include <stdint.h>
#include <math.h>

#define T_TOK 2048
#define DMODEL 1024
#define HID 2048
#define NEXP 8
#define PADROWS 5120          // 4096 routed rows + per-expert pad to 128
#define MAXTILE 40            // PADROWS / 128

// ======================= scratch (device globals) =======================
__device__ int   g_cnt[NEXP];
__device__ int   g_fill[NEXP];
__device__ int   g_off[NEXP + 1];     // padded offsets (multiples of 128)
__device__ int   g_tok[PADROWS];      // routed row -> token (-1 = pad)
__device__ int   g_pos[2 * T_TOK];    // (t,k) -> routed row
__device__ int   g_topi[2 * T_TOK];
__device__ float g_topw[2 * T_TOK];

// tiled fp16 operands: each (tile, kchunk) block = 128 rows x 64 cols = 16KB,
// SW128-swizzled within 128B rows. Contiguous per block -> cp.async.bulk.
__device__ __align__(128) __half g_At[(size_t)MAXTILE * 16 * 8192];
__device__ __align__(128) __half g_Ht[(size_t)MAXTILE * 32 * 8192];
__device__ __align__(128) __half g_W1t[(size_t)NEXP * 16 * 16 * 8192];
__device__ __align__(128) __half g_W2t[(size_t)NEXP * 8 * 32 * 8192];
__device__ float g_Y[(size_t)PADROWS * DMODEL];

// ======================= helpers =======================
__device__ __forceinline__ uint32_t smem_u32(const void* p) {
    uint32_t a;
    asm("{ .reg .u64 t; cvta.to.shared.u64 t, %1; cvt.u32.u64 %0, t; }" : "=r"(a) : "l"(p));
    return a;
}
__device__ __forceinline__ void bulkcp(uint32_t dst, const void* src,
                                       uint32_t bytes, uint32_t mbar) {
    asm volatile(
        "cp.async.bulk.shared::cta.global.mbarrier::complete_tx::bytes "
        "[%0], [%1], %2, [%3];"
        :: "r"(dst), "l"(src), "r"(bytes), "r"(mbar) : "memory");
}
#define FENCE_PROXY_ASYNC() asm volatile("fence.proxy.async.shared::cta;" ::: "memory")
#define MBARRIER_INIT(a, c) \
    asm volatile("mbarrier.init.shared.b64 [%0], %1;" :: "r"((uint32_t)(a)), "r"((uint32_t)(c)) : "memory")
#define MBARRIER_EXPECT_TX(a, b) \
    asm volatile("mbarrier.arrive.expect_tx.shared.b64 _, [%0], %1;" :: "r"((uint32_t)(a)), "r"((uint32_t)(b)) : "memory")
#define MBARRIER_WAIT_PARITY(mbar_smem_addr, phase_parity) do { \
    uint32_t _mbar = (uint32_t)(mbar_smem_addr); \
    uint32_t _parity = (uint32_t)(phase_parity); \
    uint32_t _done; \
    asm volatile( \
        "{\n\t.reg .pred p;\n\t" \
        "mbarrier.try_wait.parity.acquire.cta.shared::cta.b64 p, [%1], %2;\n\t" \
        "selp.b32 %0, 1, 0, p;\n\t}" \
        : "=r"(_done) : "r"(_mbar), "r"(_parity) : "memory"); \
    if (!_done) { \
        asm volatile( \
            "{\n\t.reg .pred P1;\n\t" \
            "WAIT_LOOP_%=:\n\t" \
            "mbarrier.try_wait.parity.acquire.cta.shared::cta.b64 P1, [%0], %1, 0x989680;\n\t" \
            "@P1 bra.uni WAIT_DONE_%=;\n\t" \
            "bra.uni WAIT_LOOP_%=;\n\t" \
            "WAIT_DONE_%=:\n\t}" \
            :: "r"(_mbar), "r"(_parity) : "memory"); \
    } \
} while (0)

__device__ __forceinline__ void ldsm_x4(uint32_t* r, uint32_t addr) {
    asm volatile("ldmatrix.sync.aligned.m8n8.x4.shared.b16 {%0,%1,%2,%3}, [%4];"
                 : "=r"(r[0]), "=r"(r[1]), "=r"(r[2]), "=r"(r[3]) : "r"(addr));
}
__device__ __forceinline__ void mma16816(float* d, const uint32_t* a, const uint32_t* b) {
    asm volatile(
        "mma.sync.aligned.m16n8k16.row.col.f32.f16.f16.f32 "
        "{%0,%1,%2,%3}, {%4,%5,%6,%7}, {%8,%9}, {%0,%1,%2,%3};"
        : "+f"(d[0]), "+f"(d[1]), "+f"(d[2]), "+f"(d[3])
        : "r"(a[0]), "r"(a[1]), "r"(a[2]), "r"(a[3]), "r"(b[0]), "r"(b[1]));
}
__device__ __forceinline__ uint32_t packh2(float a, float b) {
    __half2 h = __halves2half2(__float2half_rn(a), __float2half_rn(b));
    return *reinterpret_cast<uint32_t*>(&h);
}
// swizzled byte offset within a 128B tile row
__device__ __forceinline__ uint32_t swz(uint32_t boff, uint32_t row) {
    return boff ^ ((row & 7u) << 4);
}

// ======================= routing =======================
__global__ void zero_kernel() {
    int i = blockIdx.x * 256 + threadIdx.x;
    if (i < PADROWS) g_tok[i] = -1;
    if (i < NEXP) { g_cnt[i] = 0; g_fill[i] = 0; }
}

__global__ void scan_kernel() {
    g_off[0] = 0;
    for (int e = 0; e < NEXP; e++)
        g_off[e + 1] = g_off[e] + ((g_cnt[e] + 127) & ~127);
}

__global__ void scatter_kernel() {
    int t = blockIdx.x * blockDim.x + threadIdx.x;
    if (t >= T_TOK) return;
    #pragma unroll
    for (int k = 0; k < 2; k++) {
        int e = g_topi[2 * t + k];
        int p = g_off[e] + atomicAdd(&g_fill[e], 1);
        g_tok[p] = t;
        g_pos[2 * t + k] = p;
    }
}

__global__ void gate_kernel(const float* __restrict__ X,
                            const float* __restrict__ Wg,
                            const float* __restrict__ bg,
                            float* __restrict__ out) {
    int gwarp = (blockIdx.x * blockDim.x + threadIdx.x) >> 5;
    int lane = threadIdx.x & 31;
    if (gwarp >= T_TOK) return;
    int t = gwarp;
    float p[NEXP];
    #pragma unroll
    for (int e = 0; e < NEXP; e++) p[e] = 0.0f;
    for (int d = lane; d < DMODEL; d += 32) {
        float x = X[(size_t)t * DMODEL + d];
        const float* w = Wg + (size_t)d * NEXP;
        #pragma unroll
        for (int e = 0; e < NEXP; e++) p[e] += x * w[e];
    }
    #pragma unroll
    for (int s = 16; s > 0; s >>= 1)
        #pragma unroll
        for (int e = 0; e < NEXP; e++)
            p[e] += __shfl_xor_sync(0xFFFFFFFF, p[e], s);
    if (lane == 0) {
        float lg[NEXP];
        #pragma unroll
        for (int e = 0; e < NEXP; e++) lg[e] = p[e] + bg[e];
        int i0 = 0; float v0 = lg[0];
        #pragma unroll
        for (int e = 1; e < NEXP; e++) if (lg[e] > v0) { v0 = lg[e]; i0 = e; }
        int i1 = -1; float v1 = -3.4e38f;
        #pragma unroll
        for (int e = 0; e < NEXP; e++)
            if (e != i0 && lg[e] > v1) { v1 = lg[e]; i1 = e; }
        float ex = expf(v1 - v0);
        float inv = 1.0f / (1.0f + ex);
        g_topi[2 * t] = i0;     g_topi[2 * t + 1] = i1;
        g_topw[2 * t] = inv;    g_topw[2 * t + 1] = ex * inv;
        atomicAdd(&g_cnt[i0], 1);
        atomicAdd(&g_cnt[i1], 1);
        out[(size_t)T_TOK * DMODEL + 2 * t]     = (float)i0;
        out[(size_t)T_TOK * DMODEL + 2 * t + 1] = (float)i1;
    }
}

// ======================= fused prep: atile + wtile1 + wtile2 ======
// block b: [0,640) atile; [640,2688) wtile W1; [2688,4736) wtile W2.
__device__ __forceinline__ void atile_body(const float* __restrict__ X,
                                           int tile, int kc) {
    int row = threadIdx.x >> 1;
    int half = threadIdx.x & 1;
    int p = tile * 128 + row;
    int tok = g_tok[p];

    float v[32];
    if (tok >= 0) {
        const float* src = X + (size_t)tok * DMODEL + kc * 64 + half * 32;
        #pragma unroll
        for (int j = 0; j < 32; j += 4) {
            float4 f = *reinterpret_cast<const float4*>(src + j);
            v[j] = f.x; v[j + 1] = f.y; v[j + 2] = f.z; v[j + 3] = f.w;
        }
    } else {
        #pragma unroll
        for (int j = 0; j < 32; j++) v[j] = 0.0f;
    }

    size_t base = ((size_t)tile * 16 + kc) * 8192 + (size_t)row * 64;
    #pragma unroll
    for (int u = 0; u < 4; u++) {
        uint32_t w[4];
        #pragma unroll
        for (int q = 0; q < 4; q++)
            w[q] = packh2(v[u * 8 + q * 2], v[u * 8 + q * 2 + 1]);
        uint32_t bo = swz(half * 64 + u * 16, row);
        *reinterpret_cast<uint4*>(reinterpret_cast<char*>(g_At + base) + bo) =
            make_uint4(w[0], w[1], w[2], w[3]);
    }
}

__device__ __forceinline__ void wtile_body(const float* __restrict__ W,
                                           __half* __restrict__ O,
                                           int KD, int ND, int nb, int kc, int e,
                                           float (*s)[132]) {
    const float* Wp = W + (size_t)e * KD * ND + (size_t)kc * 64 * ND + nb * 128;
    int tid = threadIdx.x;
    // 8192 floats = 2048 float4; 256 threads x 8 float4
    #pragma unroll
    for (int i = 0; i < 8; i++) {
        int idx4 = tid + i * 256;         // 0..2047
        int kk = idx4 >> 5;               // 64 rows
        int n4 = idx4 & 31;               // 32 float4 per row
        float4 f = *reinterpret_cast<const float4*>(Wp + (size_t)kk * ND + n4 * 4);
        s[kk][n4 * 4]     = f.x;
        s[kk][n4 * 4 + 1] = f.y;
        s[kk][n4 * 4 + 2] = f.z;
        s[kk][n4 * 4 + 3] = f.w;
    }
    __syncthreads();
    int nkch = KD >> 6;
    size_t base = (((size_t)e * (ND >> 7) + nb) * nkch + kc) * 8192;
    #pragma unroll
    for (int i = 0; i < 4; i++) {
        int uu = tid + i * 256;           // 0..1023
        int r = uu >> 3, seg = uu & 7;
        uint32_t w[4];
        #pragma unroll
        for (int q = 0; q < 4; q++)
            w[q] = packh2(s[seg * 8 + q * 2][r], s[seg * 8 + q * 2 + 1][r]);
        uint32_t bo = swz(seg * 16, r);
        *reinterpret_cast<uint4*>(reinterpret_cast<char*>(O + base) + (size_t)r * 128 + bo) =
            make_uint4(w[0], w[1], w[2], w[3]);
    }
}

__global__ void prep_kernel(const float* __restrict__ X,
                            const float* __restrict__ W1,
                            const float* __restrict__ W2) {
    __shared__ float s[64][132];
    int b = blockIdx.x;
    if (b < 640) {
        atile_body(X, b >> 4, b & 15);
    } else if (b < 2688) {
        int idx = b - 640;                 // 16 nb x 16 kc x 8 e
        wtile_body(W1, g_W1t, DMODEL, HID, idx & 15, (idx >> 4) & 15, idx >> 8, s);
    } else {
        int idx = b - 2688;                // 8 nb x 32 kc x 8 e
        wtile_body(W2, g_W2t, HID, DMODEL, idx & 7, (idx >> 3) & 31, idx >> 8, s);
    }
}

// ======================= GEMM: 3-stage bulk pipeline, fp16 (R10 config) =======================
// LAYER=0: A = g_At, B = g_W1t, gelu epilogue -> tiled H (fp16).
// LAYER=1: A = g_Ht, B = g_W2t, plain epilogue -> g_Y (fp32).
#define PLANE 16384
#define STAGE (2 * PLANE)         // 32KB (A + B)
#define NST 3
#define GSMEM (NST * STAGE + 64)  // 98368

template <int NKCH, int NDIM, int LAYER>
__global__ void __launch_bounds__(256)
tc_gemm(const float* __restrict__ biasBase) {
    const int e = blockIdx.z;
    const int m0 = blockIdx.x * 128;
    if (m0 >= g_cnt[e]) return;
    const int p0 = g_off[e] + m0;           // multiple of 128
    const int tile = p0 >> 7;
    const int by = blockIdx.y;

    extern __shared__ __align__(128) char smem[];
    const uint32_t sb = smem_u32(smem);
    const uint32_t mb = sb + NST * STAGE;
    const int tid = threadIdx.x;
    const int wid = tid >> 5;
    const int lane = tid & 31;

    if (tid == 0) {
        MBARRIER_INIT(mb, 1);
        MBARRIER_INIT(mb + 8, 1);
        MBARRIER_INIT(mb + 16, 1);
        FENCE_PROXY_ASYNC();
    }
    __syncthreads();

    // device-side symbol references (NEVER passed from host)
    const __half* Ab = (LAYER == 0) ? g_At : g_Ht;
    const __half* Bb = (LAYER == 0) ? g_W1t : g_W2t;

    const __half* asrc = Ab + (size_t)tile * NKCH * 8192;
    const __half* bsrc = Bb + (((size_t)e * (NDIM >> 7) + by) * NKCH) * 8192;

    // prologue: chunks 0 and 1 into stages 0 and 1
    if (tid == 0) {
        #pragma unroll
        for (int s = 0; s < 2; s++) {
            uint32_t so = sb + s * STAGE;
            size_t go = (size_t)s * 8192;
            MBARRIER_EXPECT_TX(mb + s * 8, 2 * PLANE);
            bulkcp(so,         asrc + go, PLANE, mb + s * 8);
            bulkcp(so + PLANE, bsrc + go, PLANE, mb + s * 8);
        }
    }

    float acc[4][4][4];
    #pragma unroll
    for (int mi = 0; mi < 4; mi++)
        #pragma unroll
        for (int ni = 0; ni < 4; ni++)
            #pragma unroll
            for (int j = 0; j < 4; j++) acc[mi][ni][j] = 0.0f;

    const int wm = wid & 1;
    const int wn = wid >> 1;
    const uint32_t a_row = wm * 64 + (lane & 15);
    const uint32_t b_row = wn * 32 + (lane & 7);
    const uint32_t a_sw = (lane >> 4) * 16;
    const uint32_t b_sw = (lane >> 3) * 16;

    for (int c = 0; c < NKCH; c++) {
        int st = c % NST;
        if (c + 2 < NKCH && tid == 0) {
            int sn = (c + 2) % NST;
            uint32_t so = sb + sn * STAGE;
            uint32_t mbn = mb + sn * 8;
            size_t go = (size_t)(c + 2) * 8192;
            MBARRIER_EXPECT_TX(mbn, 2 * PLANE);
            bulkcp(so,         asrc + go, PLANE, mbn);
            bulkcp(so + PLANE, bsrc + go, PLANE, mbn);
        }
        MBARRIER_WAIT_PARITY(mb + st * 8, (c / NST) & 1);

        uint32_t stg = sb + st * STAGE;
        #pragma unroll
        for (int pair = 0; pair < 2; pair++) {
            uint32_t bfr[4][4];
            #pragma unroll
            for (int ni = 0; ni < 4; ni++) {
                uint32_t r = b_row + ni * 8;
                ldsm_x4(bfr[ni], stg + PLANE + r * 128 + swz(pair * 64 + b_sw, r));
            }
            #pragma unroll
            for (int s2 = 0; s2 < 2; s2++) {
                int ks = pair * 2 + s2;
                uint32_t afr[4][4];
                #pragma unroll
                for (int mi = 0; mi < 4; mi++) {
                    uint32_t r = a_row + mi * 16;
                    ldsm_x4(afr[mi], stg + r * 128 + swz(ks * 32 + a_sw, r));
                }
                #pragma unroll
                for (int mi = 0; mi < 4; mi++)
                    #pragma unroll
                    for (int ni = 0; ni < 4; ni++)
                        mma16816(acc[mi][ni], afr[mi], &bfr[ni][2 * s2]);
            }
        }
        __syncthreads();   // stage st free for refill at c+3
    }

    // ---- epilogue ----
    const float* bias = biasBase + (size_t)e * NDIM;
    #pragma unroll
    for (int mi = 0; mi < 4; mi++) {
        #pragma unroll
        for (int half = 0; half < 2; half++) {
            int ml = wm * 64 + mi * 16 + (lane >> 2) + half * 8;
            #pragma unroll
            for (int ni = 0; ni < 4; ni++) {
                int n = by * 128 + wn * 32 + ni * 8 + (lane & 3) * 2;
                float v0 = acc[mi][ni][half * 2]     + bias[n];
                float v1 = acc[mi][ni][half * 2 + 1] + bias[n + 1];
                if (LAYER == 0) {
                    float c0 = v0 * v0 * v0, c1 = v1 * v1 * v1;
                    v0 = 0.5f * v0 * (1.0f + tanhf(0.7978845608028654f * (v0 + 0.044715f * c0)));
                    v1 = 0.5f * v1 * (1.0f + tanhf(0.7978845608028654f * (v1 + 0.044715f * c1)));
                    size_t bbase = (((size_t)tile * 32 + (n >> 6)) * 128 + ml) * 128;
                    uint32_t bo = swz((n & 63) * 2, ml);
                    *reinterpret_cast<uint32_t*>(
                        reinterpret_cast<char*>(g_Ht) + bbase + bo) = packh2(v0, v1);
                } else {
                    float2 f; f.x = v0; f.y = v1;
                    *reinterpret_cast<float2*>(&g_Y[(size_t)(p0 + ml) * NDIM + n]) = f;
                }
            }
        }
    }
}

// ======================= combine =======================
__global__ void combine_kernel(float* __restrict__ out) {
    int i = blockIdx.x * 256 + threadIdx.x;
    int t = i >> 10;
    int d = i & 1023;
    int p0 = g_pos[2 * t], p1 = g_pos[2 * t + 1];
    float w0 = g_topw[2 * t], w1 = g_topw[2 * t + 1];
    out[i] = w0 * g_Y[(size_t)p0 * DMODEL + d] +
             w1 * g_Y[(size_t)p1 * DMODEL + d];
}

// ======================= launch =======================
extern "C" void kernel_launch(void* const* d_in, const int* in_sizes, int n_in,
                              void* d_out, int out_size) {
    const float* X  = (const float*)d_in[0];
    const float* Wg = (const float*)d_in[1];
    const float* bg = (const float*)d_in[2];
    const float* W1 = (const float*)d_in[3];
    const float* b1 = (const float*)d_in[4];
    const float* W2 = (const float*)d_in[5];
    const float* b2 = (const float*)d_in[6];
    float* out = (float*)d_out;

    cudaFuncSetAttribute(tc_gemm<16, HID, 0>,
                         cudaFuncAttributeMaxDynamicSharedMemorySize, GSMEM);
    cudaFuncSetAttribute(tc_gemm<32, DMODEL, 1>,
                         cudaFuncAttributeMaxDynamicSharedMemorySize, GSMEM);

    zero_kernel<<<20, 256>>>();
    gate_kernel<<<T_TOK / 8, 256>>>(X, Wg, bg, out);
    scan_kernel<<<1, 1>>>();
    scatter_kernel<<<8, 256>>>();

    prep_kernel<<<4736, 256>>>(X, W1, W2);

    // per-expert counts are ~512 +- 21 (binomial); 6 tiles = 768 rows = 12 sigma
    tc_gemm<16, HID, 0>
        <<<dim3(6, HID / 128, NEXP), 256, GSMEM>>>(b1);
    tc_gemm<32, DMODEL, 1>
        <<<dim3(6, DMODEL / 128, NEXP), 256, GSMEM>>>(b2);

    combine_kernel<<<(T_TOK * DMODEL) / 256, 256>>>(out);
}

// round 14
// speedup vs baseline: 1.1834x; 1.0185x over previous
#include <cuda_runtime.h>
#include <cuda_fp16.h>
#include <stdint.h>
#include <math.h>

#define T_TOK 2048
#define DMODEL 1024
#define HID 2048
#define NEXP 8
#define PADROWS 5120          // 4096 routed rows + per-expert pad to 128
#define MAXTILE 40            // PADROWS / 128

// ======================= scratch (device globals) =======================
__device__ int   g_cnt[NEXP];
__device__ int   g_fill[NEXP];
__device__ int   g_off[NEXP + 1];     // padded offsets (multiples of 128)
__device__ int   g_tok[PADROWS];      // routed row -> token (-1 = pad)
__device__ int   g_pos[2 * T_TOK];    // (t,k) -> routed row
__device__ int   g_topi[2 * T_TOK];
__device__ float g_topw[2 * T_TOK];

// tiled fp16 operands: each (tile, kchunk) block = 128 rows x 64 cols = 16KB,
// SW128-swizzled within 128B rows. Contiguous per block -> cp.async.bulk.
__device__ __align__(128) __half g_At[(size_t)MAXTILE * 16 * 8192];
__device__ __align__(128) __half g_Ht[(size_t)MAXTILE * 32 * 8192];
__device__ __align__(128) __half g_W1t[(size_t)NEXP * 16 * 16 * 8192];
__device__ __align__(128) __half g_W2t[(size_t)NEXP * 8 * 32 * 8192];
__device__ float g_Y[(size_t)PADROWS * DMODEL];

// ======================= helpers =======================
__device__ __forceinline__ uint32_t smem_u32(const void* p) {
    uint32_t a;
    asm("{ .reg .u64 t; cvta.to.shared.u64 t, %1; cvt.u32.u64 %0, t; }" : "=r"(a) : "l"(p));
    return a;
}
__device__ __forceinline__ void bulkcp(uint32_t dst, const void* src,
                                       uint32_t bytes, uint32_t mbar) {
    asm volatile(
        "cp.async.bulk.shared::cta.global.mbarrier::complete_tx::bytes "
        "[%0], [%1], %2, [%3];"
        :: "r"(dst), "l"(src), "r"(bytes), "r"(mbar) : "memory");
}
#define FENCE_PROXY_ASYNC() asm volatile("fence.proxy.async.shared::cta;" ::: "memory")
#define MBARRIER_INIT(a, c) \
    asm volatile("mbarrier.init.shared.b64 [%0], %1;" :: "r"((uint32_t)(a)), "r"((uint32_t)(c)) : "memory")
#define MBARRIER_EXPECT_TX(a, b) \
    asm volatile("mbarrier.arrive.expect_tx.shared.b64 _, [%0], %1;" :: "r"((uint32_t)(a)), "r"((uint32_t)(b)) : "memory")
#define MBARRIER_WAIT_PARITY(mbar_smem_addr, phase_parity) do { \
    uint32_t _mbar = (uint32_t)(mbar_smem_addr); \
    uint32_t _parity = (uint32_t)(phase_parity); \
    uint32_t _done; \
    asm volatile( \
        "{\n\t.reg .pred p;\n\t" \
        "mbarrier.try_wait.parity.acquire.cta.shared::cta.b64 p, [%1], %2;\n\t" \
        "selp.b32 %0, 1, 0, p;\n\t}" \
        : "=r"(_done) : "r"(_mbar), "r"(_parity) : "memory"); \
    if (!_done) { \
        asm volatile( \
            "{\n\t.reg .pred P1;\n\t" \
            "WAIT_LOOP_%=:\n\t" \
            "mbarrier.try_wait.parity.acquire.cta.shared::cta.b64 P1, [%0], %1, 0x989680;\n\t" \
            "@P1 bra.uni WAIT_DONE_%=;\n\t" \
            "bra.uni WAIT_LOOP_%=;\n\t" \
            "WAIT_DONE_%=:\n\t}" \
            :: "r"(_mbar), "r"(_parity) : "memory"); \
    } \
} while (0)

__device__ __forceinline__ void ldsm_x4(uint32_t* r, uint32_t addr) {
    asm volatile("ldmatrix.sync.aligned.m8n8.x4.shared.b16 {%0,%1,%2,%3}, [%4];"
                 : "=r"(r[0]), "=r"(r[1]), "=r"(r[2]), "=r"(r[3]) : "r"(addr));
}
__device__ __forceinline__ void mma16816(float* d, const uint32_t* a, const uint32_t* b) {
    asm volatile(
        "mma.sync.aligned.m16n8k16.row.col.f32.f16.f16.f32 "
        "{%0,%1,%2,%3}, {%4,%5,%6,%7}, {%8,%9}, {%0,%1,%2,%3};"
        : "+f"(d[0]), "+f"(d[1]), "+f"(d[2]), "+f"(d[3])
        : "r"(a[0]), "r"(a[1]), "r"(a[2]), "r"(a[3]), "r"(b[0]), "r"(b[1]));
}
__device__ __forceinline__ uint32_t packh2(float a, float b) {
    __half2 h = __halves2half2(__float2half_rn(a), __float2half_rn(b));
    return *reinterpret_cast<uint32_t*>(&h);
}
// swizzled byte offset within a 128B tile row
__device__ __forceinline__ uint32_t swz(uint32_t boff, uint32_t row) {
    return boff ^ ((row & 7u) << 4);
}

// ======================= K1: fused gate + g_tok zero + wtile =======================
// blocks [0,256): gate; [256,276): zero g_tok; [276,2324): wtile W1; [2324,4372): wtile W2.
__device__ __forceinline__ void gate_body(const float* __restrict__ X,
                                          const float* __restrict__ Wg,
                                          const float* __restrict__ bg,
                                          float* __restrict__ out, int blk) {
    int gwarp = (blk * 256 + threadIdx.x) >> 5;   // token id
    int lane = threadIdx.x & 31;
    int t = gwarp;
    float p[NEXP];
    #pragma unroll
    for (int e = 0; e < NEXP; e++) p[e] = 0.0f;
    for (int d = lane; d < DMODEL; d += 32) {
        float x = X[(size_t)t * DMODEL + d];
        const float* w = Wg + (size_t)d * NEXP;
        #pragma unroll
        for (int e = 0; e < NEXP; e++) p[e] += x * w[e];
    }
    #pragma unroll
    for (int s = 16; s > 0; s >>= 1)
        #pragma unroll
        for (int e = 0; e < NEXP; e++)
            p[e] += __shfl_xor_sync(0xFFFFFFFF, p[e], s);
    if (lane == 0) {
        float lg[NEXP];
        #pragma unroll
        for (int e = 0; e < NEXP; e++) lg[e] = p[e] + bg[e];
        int i0 = 0; float v0 = lg[0];
        #pragma unroll
        for (int e = 1; e < NEXP; e++) if (lg[e] > v0) { v0 = lg[e]; i0 = e; }
        int i1 = -1; float v1 = -3.4e38f;
        #pragma unroll
        for (int e = 0; e < NEXP; e++)
            if (e != i0 && lg[e] > v1) { v1 = lg[e]; i1 = e; }
        float ex = expf(v1 - v0);
        float inv = 1.0f / (1.0f + ex);
        g_topi[2 * t] = i0;     g_topi[2 * t + 1] = i1;
        g_topw[2 * t] = inv;    g_topw[2 * t + 1] = ex * inv;
        out[(size_t)T_TOK * DMODEL + 2 * t]     = (float)i0;
        out[(size_t)T_TOK * DMODEL + 2 * t + 1] = (float)i1;
    }
}

__device__ __forceinline__ void wtile_body(const float* __restrict__ W,
                                           __half* __restrict__ O,
                                           int KD, int ND, int nb, int kc, int e,
                                           float (*s)[132]) {
    const float* Wp = W + (size_t)e * KD * ND + (size_t)kc * 64 * ND + nb * 128;
    int tid = threadIdx.x;
    #pragma unroll
    for (int i = 0; i < 8; i++) {
        int idx4 = tid + i * 256;         // 0..2047
        int kk = idx4 >> 5;
        int n4 = idx4 & 31;
        float4 f = *reinterpret_cast<const float4*>(Wp + (size_t)kk * ND + n4 * 4);
        s[kk][n4 * 4]     = f.x;
        s[kk][n4 * 4 + 1] = f.y;
        s[kk][n4 * 4 + 2] = f.z;
        s[kk][n4 * 4 + 3] = f.w;
    }
    __syncthreads();
    int nkch = KD >> 6;
    size_t base = (((size_t)e * (ND >> 7) + nb) * nkch + kc) * 8192;
    #pragma unroll
    for (int i = 0; i < 4; i++) {
        int uu = tid + i * 256;
        int r = uu >> 3, seg = uu & 7;
        uint32_t w[4];
        #pragma unroll
        for (int q = 0; q < 4; q++)
            w[q] = packh2(s[seg * 8 + q * 2][r], s[seg * 8 + q * 2 + 1][r]);
        uint32_t bo = swz(seg * 16, r);
        *reinterpret_cast<uint4*>(reinterpret_cast<char*>(O + base) + (size_t)r * 128 + bo) =
            make_uint4(w[0], w[1], w[2], w[3]);
    }
}

__global__ void fused1_kernel(const float* __restrict__ X,
                              const float* __restrict__ Wg,
                              const float* __restrict__ bg,
                              const float* __restrict__ W1,
                              const float* __restrict__ W2,
                              float* __restrict__ out) {
    __shared__ float s[64][132];
    int b = blockIdx.x;
    if (b < 256) {
        gate_body(X, Wg, bg, out, b);
    } else if (b < 276) {
        int i = (b - 256) * 256 + threadIdx.x;
        g_tok[i] = -1;
    } else if (b < 2324) {
        int idx = b - 276;                 // 16 nb x 16 kc x 8 e
        wtile_body(W1, g_W1t, DMODEL, HID, idx & 15, (idx >> 4) & 15, idx >> 8, s);
    } else {
        int idx = b - 2324;                // 8 nb x 32 kc x 8 e
        wtile_body(W2, g_W2t, HID, DMODEL, idx & 7, (idx >> 3) & 31, idx >> 8, s);
    }
}

// ======================= K2: count + scan (1 block) =======================
__global__ void countscan_kernel() {
    __shared__ int hist[NEXP];
    int tid = threadIdx.x;
    if (tid < NEXP) hist[tid] = 0;
    __syncthreads();
    for (int i = tid; i < 2 * T_TOK; i += 256)
        atomicAdd(&hist[g_topi[i]], 1);
    __syncthreads();
    if (tid == 0) {
        int off = 0;
        g_off[0] = 0;
        for (int e = 0; e < NEXP; e++) {
            g_cnt[e] = hist[e];
            g_fill[e] = 0;
            off += (hist[e] + 127) & ~127;
            g_off[e + 1] = off;
        }
    }
}

// ======================= K3: scatter =======================
__global__ void scatter_kernel() {
    int t = blockIdx.x * blockDim.x + threadIdx.x;
    if (t >= T_TOK) return;
    #pragma unroll
    for (int k = 0; k < 2; k++) {
        int e = g_topi[2 * t + k];
        int p = g_off[e] + atomicAdd(&g_fill[e], 1);
        g_tok[p] = t;
        g_pos[2 * t + k] = p;
    }
}

// ======================= K4: atile =======================
__global__ void atile_kernel(const float* __restrict__ X) {
    int tile = blockIdx.x;
    int kc = blockIdx.y;
    int row = threadIdx.x >> 1;
    int half = threadIdx.x & 1;
    int p = tile * 128 + row;
    int tok = g_tok[p];

    float v[32];
    if (tok >= 0) {
        const float* src = X + (size_t)tok * DMODEL + kc * 64 + half * 32;
        #pragma unroll
        for (int j = 0; j < 32; j += 4) {
            float4 f = *reinterpret_cast<const float4*>(src + j);
            v[j] = f.x; v[j + 1] = f.y; v[j + 2] = f.z; v[j + 3] = f.w;
        }
    } else {
        #pragma unroll
        for (int j = 0; j < 32; j++) v[j] = 0.0f;
    }

    size_t base = ((size_t)tile * 16 + kc) * 8192 + (size_t)row * 64;
    #pragma unroll
    for (int u = 0; u < 4; u++) {
        uint32_t w[4];
        #pragma unroll
        for (int q = 0; q < 4; q++)
            w[q] = packh2(v[u * 8 + q * 2], v[u * 8 + q * 2 + 1]);
        uint32_t bo = swz(half * 64 + u * 16, row);
        *reinterpret_cast<uint4*>(reinterpret_cast<char*>(g_At + base) + bo) =
            make_uint4(w[0], w[1], w[2], w[3]);
    }
}

// ======================= GEMM: 3-stage bulk pipeline, fp16 (R10 config) =======================
#define PLANE 16384
#define STAGE (2 * PLANE)         // 32KB (A + B)
#define NST 3
#define GSMEM (NST * STAGE + 64)  // 98368

template <int NKCH, int NDIM, int LAYER>
__global__ void __launch_bounds__(256)
tc_gemm(const float* __restrict__ biasBase) {
    const int e = blockIdx.z;
    const int m0 = blockIdx.x * 128;
    if (m0 >= g_cnt[e]) return;
    const int p0 = g_off[e] + m0;           // multiple of 128
    const int tile = p0 >> 7;
    const int by = blockIdx.y;

    extern __shared__ __align__(128) char smem[];
    const uint32_t sb = smem_u32(smem);
    const uint32_t mb = sb + NST * STAGE;
    const int tid = threadIdx.x;
    const int wid = tid >> 5;
    const int lane = tid & 31;

    if (tid == 0) {
        MBARRIER_INIT(mb, 1);
        MBARRIER_INIT(mb + 8, 1);
        MBARRIER_INIT(mb + 16, 1);
        FENCE_PROXY_ASYNC();
    }
    __syncthreads();

    const __half* Ab = (LAYER == 0) ? g_At : g_Ht;
    const __half* Bb = (LAYER == 0) ? g_W1t : g_W2t;

    const __half* asrc = Ab + (size_t)tile * NKCH * 8192;
    const __half* bsrc = Bb + (((size_t)e * (NDIM >> 7) + by) * NKCH) * 8192;

    if (tid == 0) {
        #pragma unroll
        for (int s = 0; s < 2; s++) {
            uint32_t so = sb + s * STAGE;
            size_t go = (size_t)s * 8192;
            MBARRIER_EXPECT_TX(mb + s * 8, 2 * PLANE);
            bulkcp(so,         asrc + go, PLANE, mb + s * 8);
            bulkcp(so + PLANE, bsrc + go, PLANE, mb + s * 8);
        }
    }

    float acc[4][4][4];
    #pragma unroll
    for (int mi = 0; mi < 4; mi++)
        #pragma unroll
        for (int ni = 0; ni < 4; ni++)
            #pragma unroll
            for (int j = 0; j < 4; j++) acc[mi][ni][j] = 0.0f;

    const int wm = wid & 1;
    const int wn = wid >> 1;
    const uint32_t a_row = wm * 64 + (lane & 15);
    const uint32_t b_row = wn * 32 + (lane & 7);
    const uint32_t a_sw = (lane >> 4) * 16;
    const uint32_t b_sw = (lane >> 3) * 16;

    for (int c = 0; c < NKCH; c++) {
        int st = c % NST;
        if (c + 2 < NKCH && tid == 0) {
            int sn = (c + 2) % NST;
            uint32_t so = sb + sn * STAGE;
            uint32_t mbn = mb + sn * 8;
            size_t go = (size_t)(c + 2) * 8192;
            MBARRIER_EXPECT_TX(mbn, 2 * PLANE);
            bulkcp(so,         asrc + go, PLANE, mbn);
            bulkcp(so + PLANE, bsrc + go, PLANE, mbn);
        }
        MBARRIER_WAIT_PARITY(mb + st * 8, (c / NST) & 1);

        uint32_t stg = sb + st * STAGE;
        #pragma unroll
        for (int pair = 0; pair < 2; pair++) {
            uint32_t bfr[4][4];
            #pragma unroll
            for (int ni = 0; ni < 4; ni++) {
                uint32_t r = b_row + ni * 8;
                ldsm_x4(bfr[ni], stg + PLANE + r * 128 + swz(pair * 64 + b_sw, r));
            }
            #pragma unroll
            for (int s2 = 0; s2 < 2; s2++) {
                int ks = pair * 2 + s2;
                uint32_t afr[4][4];
                #pragma unroll
                for (int mi = 0; mi < 4; mi++) {
                    uint32_t r = a_row + mi * 16;
                    ldsm_x4(afr[mi], stg + r * 128 + swz(ks * 32 + a_sw, r));
                }
                #pragma unroll
                for (int mi = 0; mi < 4; mi++)
                    #pragma unroll
                    for (int ni = 0; ni < 4; ni++)
                        mma16816(acc[mi][ni], afr[mi], &bfr[ni][2 * s2]);
            }
        }
        __syncthreads();
    }

    // ---- epilogue ----
    const float* bias = biasBase + (size_t)e * NDIM;
    #pragma unroll
    for (int mi = 0; mi < 4; mi++) {
        #pragma unroll
        for (int half = 0; half < 2; half++) {
            int ml = wm * 64 + mi * 16 + (lane >> 2) + half * 8;
            #pragma unroll
            for (int ni = 0; ni < 4; ni++) {
                int n = by * 128 + wn * 32 + ni * 8 + (lane & 3) * 2;
                float v0 = acc[mi][ni][half * 2]     + bias[n];
                float v1 = acc[mi][ni][half * 2 + 1] + bias[n + 1];
                if (LAYER == 0) {
                    float c0 = v0 * v0 * v0, c1 = v1 * v1 * v1;
                    v0 = 0.5f * v0 * (1.0f + tanhf(0.7978845608028654f * (v0 + 0.044715f * c0)));
                    v1 = 0.5f * v1 * (1.0f + tanhf(0.7978845608028654f * (v1 + 0.044715f * c1)));
                    size_t bbase = (((size_t)tile * 32 + (n >> 6)) * 128 + ml) * 128;
                    uint32_t bo = swz((n & 63) * 2, ml);
                    *reinterpret_cast<uint32_t*>(
                        reinterpret_cast<char*>(g_Ht) + bbase + bo) = packh2(v0, v1);
                } else {
                    float2 f; f.x = v0; f.y = v1;
                    *reinterpret_cast<float2*>(&g_Y[(size_t)(p0 + ml) * NDIM + n]) = f;
                }
            }
        }
    }
}

// ======================= combine =======================
__global__ void combine_kernel(float* __restrict__ out) {
    int i = blockIdx.x * 256 + threadIdx.x;
    int t = i >> 10;
    int d = i & 1023;
    int p0 = g_pos[2 * t], p1 = g_pos[2 * t + 1];
    float w0 = g_topw[2 * t], w1 = g_topw[2 * t + 1];
    out[i] = w0 * g_Y[(size_t)p0 * DMODEL + d] +
             w1 * g_Y[(size_t)p1 * DMODEL + d];
}

// ======================= launch =======================
extern "C" void kernel_launch(void* const* d_in, const int* in_sizes, int n_in,
                              void* d_out, int out_size) {
    const float* X  = (const float*)d_in[0];
    const float* Wg = (const float*)d_in[1];
    const float* bg = (const float*)d_in[2];
    const float* W1 = (const float*)d_in[3];
    const float* b1 = (const float*)d_in[4];
    const float* W2 = (const float*)d_in[5];
    const float* b2 = (const float*)d_in[6];
    float* out = (float*)d_out;

    cudaFuncSetAttribute(tc_gemm<16, HID, 0>,
                         cudaFuncAttributeMaxDynamicSharedMemorySize, GSMEM);
    cudaFuncSetAttribute(tc_gemm<32, DMODEL, 1>,
                         cudaFuncAttributeMaxDynamicSharedMemorySize, GSMEM);

    // K1: gate + g_tok zero + wtile W1/W2 (independent work fused in one wave)
    fused1_kernel<<<4372, 256>>>(X, Wg, bg, W1, W2, out);
    // K2: counts + padded scan + fill reset (1 block)
    countscan_kernel<<<1, 256>>>();
    // K3: scatter
    scatter_kernel<<<8, 256>>>();
    // K4: A tiles
    atile_kernel<<<dim3(MAXTILE, 16), 256>>>(X);

    // per-expert counts are ~512 +- 21 (binomial); 6 tiles = 768 rows = 12 sigma
    tc_gemm<16, HID, 0>
        <<<dim3(6, HID / 128, NEXP), 256, GSMEM>>>(b1);
    tc_gemm<32, DMODEL, 1>
        <<<dim3(6, DMODEL / 128, NEXP), 256, GSMEM>>>(b2);

    combine_kernel<<<(T_TOK * DMODEL) / 256, 256>>>(out);
}